// round 1
// baseline (speedup 1.0000x reference)
#include <cuda_runtime.h>
#include <math.h>

#define RR 20
#define NB 4
#define HH 480
#define WWI 640
#define hh 120
#define ww 160
#define FC 32
#define DC 32
#define OC2 4

// Scratch (static device globals; no allocations)
__device__ float g_rg [RR*NB*hh*ww];
__device__ float g_ixc[RR*NB*hh*ww];
__device__ float g_iyc[RR*NB*hh*ww];
__device__ float g_feat[RR*NB*FC*hh*ww];   // 196.6 MB
__device__ float g_ad [RR*NB*DC*hh*ww];    // 196.6 MB
__device__ float g_num[RR];
__device__ float g_den[RR];

__global__ void k_zero() {
    int t = threadIdx.x;
    if (t < RR) { g_num[t] = 0.f; g_den[t] = 0.f; }
}

// -------------------- Kernel 1: random pooling + sample coords --------------------
__global__ void k_pool(const float* __restrict__ gts, const float* __restrict__ rnd) {
    int idx = blockIdx.x * blockDim.x + threadIdx.x;
    if (idx >= RR*NB*hh*ww) return;
    int j = idx % ww; int t = idx / ww;
    int i = t % hh;  t /= hh;
    int n = t % NB;  int r = t / NB;

    const float* gp = gts + n * (HH*WWI);
    const float* rp = rnd + (r*NB + n) * (HH*WWI);

    float best = -1.f; int bloc = 0; float bg = 0.f;
    #pragma unroll
    for (int bi = 0; bi < 4; bi++) {
        int off = (4*i + bi)*WWI + 4*j;
        float4 g4 = *reinterpret_cast<const float4*>(gp + off);
        float4 r4 = *reinterpret_cast<const float4*>(rp + off);
        float ga[4] = {g4.x, g4.y, g4.z, g4.w};
        float ra[4] = {r4.x, r4.y, r4.z, r4.w};
        #pragma unroll
        for (int bj = 0; bj < 4; bj++) {
            float rm = (ga[bj] > 0.1f) ? ra[bj] : 0.f;   // rand * (gt > 0.1)
            if (rm > best) { best = rm; bloc = bi*4 + bj; bg = ga[bj]; }  // argmax, first on tie
        }
    }
    int bi = bloc >> 2, bj = bloc & 3;
    int row = 4*i + bi, col = 4*j + bj;
    g_rg[idx] = (bg < 0.1f) ? 0.f : bg;

    int idx2 = row*WWI + col + 1282;           // + bias (W//w//2 + H//h//2 * W)
    int col2 = idx2 % WWI;
    int row2 = idx2 / WWI;
    float gx = 2.f * ((float)col2 / 640.f - 0.5f);
    float gy = 2.f * ((float)row2 / 480.f - 0.5f);
    g_ixc[idx] = (gx + 1.f) * 0.5f * 639.f;    // pixel-space sample coords
    g_iyc[idx] = (gy + 1.f) * 0.5f * 479.f;
}

// -------------------- Kernel 2: grid sample (x staged once, reused by all 20 iters) ----
// block: (32,4) threads, output tile 4x32; grid (5, 30, 4)
__global__ void __launch_bounds__(128) k_sample(const float* __restrict__ x) {
    __shared__ float s_x[20*132];
    __shared__ float s_ix[RR][128];
    __shared__ float s_iy[RR][128];
    int tx = threadIdx.x, ty = threadIdx.y;
    int tid = ty*32 + tx;
    int j0 = blockIdx.x * 32, i0 = blockIdx.y * 4, n = blockIdx.z;
    int i = i0 + ty, j = j0 + tx;

    for (int r = 0; r < RR; r++) {
        int gi = ((r*NB + n)*hh + i)*ww + j;
        s_ix[r][tid] = g_ixc[gi];
        s_iy[r][tid] = g_iyc[gi];
    }
    int rb = 4*i0, cb = 4*j0;

    for (int ic = 0; ic < FC; ic++) {
        const float* xp = x + (n*FC + ic) * (HH*WWI);
        __syncthreads();
        for (int t = tid; t < 20*132; t += 128) {
            int lr = t / 132, lc = t % 132;
            int gy = min(rb + lr, HH-1), gx2 = min(cb + lc, WWI-1);  // clamped staging
            s_x[t] = xp[gy*WWI + gx2];
        }
        __syncthreads();
        for (int r = 0; r < RR; r++) {
            float ixv = s_ix[r][tid], iyv = s_iy[r][tid];
            float x0f = floorf(ixv), y0f = floorf(iyv);
            float wx = ixv - x0f, wy = iyv - y0f;
            int x0 = (int)x0f, y0 = (int)y0f;
            float f00, f10, f01, f11;
            if (x0 >= cb && x0+1 <= cb+131 && y0 >= rb && y0+1 <= rb+19) {
                const float* s0 = &s_x[(y0-rb)*132 + (x0-cb)];
                f00 = s0[0]; f10 = s0[1]; f01 = s0[132]; f11 = s0[133];
            } else { // rare column-wrap case: global gather with clamp
                int xa = min(max(x0,   0), WWI-1), xb = min(max(x0+1, 0), WWI-1);
                int ya = min(max(y0,   0), HH-1),  yb = min(max(y0+1, 0), HH-1);
                f00 = xp[ya*WWI+xa]; f10 = xp[ya*WWI+xb];
                f01 = xp[yb*WWI+xa]; f11 = xp[yb*WWI+xb];
            }
            bool okx0 = (x0 >= 0) && (x0 <= WWI-1);
            bool okx1 = (x0+1 <= WWI-1);
            bool oky0 = (y0 >= 0) && (y0 <= HH-1);
            bool oky1 = (y0+1 <= HH-1);
            float w00 = (1.f-wx)*(1.f-wy); if (!(okx0 && oky0)) w00 = 0.f;
            float w10 = wx*(1.f-wy);       if (!(okx1 && oky0)) w10 = 0.f;
            float w01 = (1.f-wx)*wy;       if (!(okx0 && oky1)) w01 = 0.f;
            float w11 = wx*wy;             if (!(okx1 && oky1)) w11 = 0.f;
            float v = f00*w00 + f10*w10 + f01*w01 + f11*w11;
            g_feat[(((r*NB + n)*FC + ic)*hh + i)*ww + j] = v;
        }
    }
}

// -------------------- Kernel 3: conv3x3 32->32 + sigmoid + * d  ->  g_ad --------------
// block (8,8,4)=256; output tile 8x32 spatial, all 32 oc; ic chunked by 16 (smem < 48KB)
__global__ void __launch_bounds__(256) k_conv1(const float* __restrict__ Wa,
                                               const float* __restrict__ ba,
                                               const float* __restrict__ dd) {
    __shared__ float s_f[16*10*36];
    __shared__ float s_w[DC*16*9];
    int tx = threadIdx.x, ty = threadIdx.y, tz = threadIdx.z;
    int tid = tx + ty*8 + tz*64;
    int j0 = blockIdx.x*32, i0 = blockIdx.y*8, z = blockIdx.z;  // z = r*NB + n
    int n = z & (NB-1);

    float acc[8][4];
    #pragma unroll
    for (int u = 0; u < 8; u++) {
        float b = ba[tz*8 + u];
        #pragma unroll
        for (int p = 0; p < 4; p++) acc[u][p] = b;
    }

    for (int cc = 0; cc < 2; cc++) {
        __syncthreads();
        for (int t = tid; t < 16*10*34; t += 256) {
            int lc = t % 34; int t2 = t / 34; int lr = t2 % 10; int icl = t2 / 10;
            int gi = i0 - 1 + lr, gj = j0 - 1 + lc;
            float v = 0.f;
            if (gi >= 0 && gi < hh && gj >= 0 && gj < ww)
                v = g_feat[((z*FC + cc*16 + icl)*hh + gi)*ww + gj];
            s_f[(icl*10 + lr)*36 + lc] = v;
        }
        for (int t = tid; t < DC*16*9; t += 256) {
            int k = t % 9; int t2 = t / 9; int icl = t2 % 16; int oc = t2 / 16;
            s_w[t] = Wa[(oc*FC + cc*16 + icl)*9 + k];
        }
        __syncthreads();
        for (int icl = 0; icl < 16; icl++) {
            #pragma unroll
            for (int dy = 0; dy < 3; dy++) {
                const float* fr = &s_f[(icl*10 + ty + dy)*36 + tx*4];
                float4 fa = *reinterpret_cast<const float4*>(fr);
                float2 fb = *reinterpret_cast<const float2*>(fr + 4);
                float fv[6] = {fa.x, fa.y, fa.z, fa.w, fb.x, fb.y};
                #pragma unroll
                for (int dx = 0; dx < 3; dx++) {
                    #pragma unroll
                    for (int u = 0; u < 8; u++) {
                        float wv = s_w[((tz*8 + u)*16 + icl)*9 + dy*3 + dx];
                        acc[u][0] += fv[dx  ]*wv;
                        acc[u][1] += fv[dx+1]*wv;
                        acc[u][2] += fv[dx+2]*wv;
                        acc[u][3] += fv[dx+3]*wv;
                    }
                }
            }
        }
    }
    int i = i0 + ty;
    #pragma unroll
    for (int u = 0; u < 8; u++) {
        int oc = tz*8 + u;
        #pragma unroll
        for (int p = 0; p < 4; p++) {
            int j = j0 + tx*4 + p;
            float att = 1.f / (1.f + expf(-acc[u][p]));
            float dv = dd[((n*DC + oc)*hh + i)*ww + j];
            g_ad[((z*DC + oc)*hh + i)*ww + j] = att * dv;
        }
    }
}

// -------------------- Kernel 4: conv3x3 32->4 + log-grad smooth-L1 loss ---------------
// block (8,8,2)=128; output tile 8x32; per thread 2 oc x 4 positions
__global__ void __launch_bounds__(128) k_conv2(const float* __restrict__ Wp,
                                               const float* __restrict__ bp) {
    __shared__ float s_a[16*10*36];
    __shared__ float s_w2[OC2*DC*9];
    __shared__ float s_rg[10*36];
    __shared__ float s_red[8];
    int tx = threadIdx.x, ty = threadIdx.y, tz = threadIdx.z;
    int tid = tx + ty*8 + tz*64;
    int j0 = blockIdx.x*32, i0 = blockIdx.y*8, z = blockIdx.z;
    int r = z >> 2;

    for (int t = tid; t < 10*34; t += 128) {
        int lc = t % 34, lr = t / 34;
        int gi = i0 - 1 + lr, gj = j0 - 1 + lc;
        float v = 0.f;
        if (gi >= 0 && gi < hh && gj >= 0 && gj < ww) v = g_rg[(z*hh + gi)*ww + gj];
        s_rg[lr*36 + lc] = v;
    }
    for (int t = tid; t < OC2*DC*9; t += 128) s_w2[t] = Wp[t];

    float acc[2][4];
    #pragma unroll
    for (int u = 0; u < 2; u++) {
        float b = bp[tz*2 + u];
        #pragma unroll
        for (int p = 0; p < 4; p++) acc[u][p] = b;
    }

    for (int cc = 0; cc < 2; cc++) {
        __syncthreads();
        for (int t = tid; t < 16*10*34; t += 128) {
            int lc = t % 34; int t2 = t / 34; int lr = t2 % 10; int icl = t2 / 10;
            int gi = i0 - 1 + lr, gj = j0 - 1 + lc;
            float v = 0.f;
            if (gi >= 0 && gi < hh && gj >= 0 && gj < ww)
                v = g_ad[((z*DC + cc*16 + icl)*hh + gi)*ww + gj];
            s_a[(icl*10 + lr)*36 + lc] = v;
        }
        __syncthreads();
        for (int icl = 0; icl < 16; icl++) {
            #pragma unroll
            for (int dy = 0; dy < 3; dy++) {
                const float* fr = &s_a[(icl*10 + ty + dy)*36 + tx*4];
                float4 fa = *reinterpret_cast<const float4*>(fr);
                float2 fb = *reinterpret_cast<const float2*>(fr + 4);
                float fv[6] = {fa.x, fa.y, fa.z, fa.w, fb.x, fb.y};
                #pragma unroll
                for (int dx = 0; dx < 3; dx++) {
                    #pragma unroll
                    for (int u = 0; u < 2; u++) {
                        float wv = s_w2[((tz*2 + u)*DC + cc*16 + icl)*9 + dy*3 + dx];
                        acc[u][0] += fv[dx  ]*wv;
                        acc[u][1] += fv[dx+1]*wv;
                        acc[u][2] += fv[dx+2]*wv;
                        acc[u][3] += fv[dx+3]*wv;
                    }
                }
            }
        }
    }

    // loss: grad channels (ox,oy) = (0,1),(1,1),(1,0),(1,-1)
    float num = 0.f, den = 0.f;
    #pragma unroll
    for (int u = 0; u < 2; u++) {
        int oc = tz*2 + u;
        int ox = (oc >= 1) ? 1 : 0;
        int oy = (oc < 2) ? 1 : ((oc == 2) ? 0 : -1);
        #pragma unroll
        for (int p = 0; p < 4; p++) {
            int lri = ty + 1, lci = tx*4 + p + 1;
            float c   = s_rg[lri*36 + lci];
            float nbv = s_rg[(lri + ox)*36 + (lci + oy)];
            float grad = logf(c + 1e-6f) - logf(nbv + 1e-6f);
            float a = fabsf(acc[u][p] - grad);
            float sl1 = (a < 0.01f) ? (0.5f*a*a/0.01f) : (a - 0.5f*0.01f);
            if (c > 0.1f && nbv > 0.1f) { num += sl1; den += 1.f; }
        }
    }
    #pragma unroll
    for (int o = 16; o > 0; o >>= 1) {
        num += __shfl_down_sync(0xffffffffu, num, o);
        den += __shfl_down_sync(0xffffffffu, den, o);
    }
    int wid = tid >> 5, lid = tid & 31;
    if (lid == 0) { s_red[wid] = num; s_red[4 + wid] = den; }
    __syncthreads();
    if (tid == 0) {
        atomicAdd(&g_num[r], s_red[0] + s_red[1] + s_red[2] + s_red[3]);
        atomicAdd(&g_den[r], s_red[4] + s_red[5] + s_red[6] + s_red[7]);
    }
}

__global__ void k_final(float* out) {
    if (threadIdx.x == 0) {
        float tot = 0.f;
        for (int r = 0; r < RR; r++) tot += g_num[r] / g_den[r];
        out[0] = tot / 20.0f;
    }
}

extern "C" void kernel_launch(void* const* d_in, const int* in_sizes, int n_in,
                              void* d_out, int out_size) {
    const float* x    = (const float*)d_in[0];
    const float* d    = (const float*)d_in[1];
    const float* gts  = (const float*)d_in[2];
    const float* rnd  = (const float*)d_in[3];
    const float* Wa   = (const float*)d_in[4];
    const float* ba   = (const float*)d_in[5];
    const float* Wp   = (const float*)d_in[6];
    const float* bp   = (const float*)d_in[7];
    float* out = (float*)d_out;

    k_zero<<<1, 32>>>();
    k_pool<<<(RR*NB*hh*ww + 255)/256, 256>>>(gts, rnd);

    dim3 bs2(32, 4), gs2(ww/32, hh/4, NB);
    k_sample<<<gs2, bs2>>>(x);

    dim3 bs3(8, 8, 4), gs3(ww/32, hh/8, RR*NB);
    k_conv1<<<gs3, bs3>>>(Wa, ba, d);

    dim3 bs4(8, 8, 2), gs4(ww/32, hh/8, RR*NB);
    k_conv2<<<gs4, bs4>>>(Wp, bp);

    k_final<<<1, 32>>>(out);
}

// round 4
// speedup vs baseline: 1.6977x; 1.6977x over previous
#include <cuda_runtime.h>
#include <cuda_bf16.h>
#include <math.h>
#include <stdint.h>

#define RR 20
#define NB 4
#define HH 480
#define WWI 640
#define hh 120
#define ww 160
#define FC 32
#define DC 32

// Scratch (static device globals; no allocations). Explicit 16B alignment —
// these are accessed through uint4 / __nv_bfloat162 casts.
__device__ float g_rg [RR*NB*hh*ww];
__device__ float g_ixc[RR*NB*hh*ww];
__device__ float g_iyc[RR*NB*hh*ww];
__device__ __align__(16) __nv_bfloat16 g_featB[RR*NB*FC*hh*ww];  // [z][ic][pos]  98MB
__device__ __align__(16) __nv_bfloat16 g_adT [RR*NB*hh*ww*DC];   // [z][pos][ic]  98MB
__device__ __align__(16) __nv_bfloat16 g_wa_b[9*32*32];          // [tap][oc][ic]
__device__ __align__(16) __nv_bfloat16 g_wp_b[9*8*32];           // [tap][oc(8,pad)][ic]
__device__ float g_num[RR];
__device__ float g_den[RR];

// ---------------- PTX helpers ----------------
#define LDSM_X4(r0,r1,r2,r3,addr) \
    asm volatile("ldmatrix.sync.aligned.m8n8.x4.shared.b16 {%0,%1,%2,%3}, [%4];" \
        : "=r"(r0),"=r"(r1),"=r"(r2),"=r"(r3) : "r"(addr))

#define LDSM_X2(r0,r1,addr) \
    asm volatile("ldmatrix.sync.aligned.m8n8.x2.shared.b16 {%0,%1}, [%2];" \
        : "=r"(r0),"=r"(r1) : "r"(addr))

#define MMA_BF16(d, a0,a1,a2,a3, b0,b1) \
    asm volatile("mma.sync.aligned.m16n8k16.row.col.f32.bf16.bf16.f32 " \
        "{%0,%1,%2,%3},{%4,%5,%6,%7},{%8,%9},{%0,%1,%2,%3};" \
        : "+f"((d)[0]),"+f"((d)[1]),"+f"((d)[2]),"+f"((d)[3]) \
        : "r"(a0),"r"(a1),"r"(a2),"r"(a3),"r"(b0),"r"(b1))

__global__ void k_zero() {
    int t = threadIdx.x;
    if (t < RR) { g_num[t] = 0.f; g_den[t] = 0.f; }
}

// ---------------- weight convert ----------------
__global__ void k_wcvt(const float* __restrict__ Wa, const float* __restrict__ Wp) {
    int t = blockIdx.x * 256 + threadIdx.x;
    if (t < 9*32*32) {
        int ic = t & 31, oc = (t >> 5) & 31, tap = t >> 10;
        g_wa_b[t] = __float2bfloat16(Wa[(oc*32 + ic)*9 + tap]);
    }
    if (t < 9*8*32) {
        int ic = t & 31, oc = (t >> 5) & 7, tap = t >> 8;
        float v = (oc < 4) ? Wp[(oc*32 + ic)*9 + tap] : 0.f;
        g_wp_b[t] = __float2bfloat16(v);
    }
}

// ---------------- Kernel 1: random pooling + sample coords ----------------
__global__ void k_pool(const float* __restrict__ gts, const float* __restrict__ rnd) {
    int idx = blockIdx.x * blockDim.x + threadIdx.x;
    if (idx >= RR*NB*hh*ww) return;
    int j = idx % ww; int t = idx / ww;
    int i = t % hh;  t /= hh;
    int n = t % NB;  int r = t / NB;

    const float* gp = gts + n * (HH*WWI);
    const float* rp = rnd + (r*NB + n) * (HH*WWI);

    float best = -1.f; int bloc = 0; float bg = 0.f;
    #pragma unroll
    for (int bi = 0; bi < 4; bi++) {
        int off = (4*i + bi)*WWI + 4*j;
        float4 g4 = *reinterpret_cast<const float4*>(gp + off);
        float4 r4 = *reinterpret_cast<const float4*>(rp + off);
        float ga[4] = {g4.x, g4.y, g4.z, g4.w};
        float ra[4] = {r4.x, r4.y, r4.z, r4.w};
        #pragma unroll
        for (int bj = 0; bj < 4; bj++) {
            float rm = (ga[bj] > 0.1f) ? ra[bj] : 0.f;
            if (rm > best) { best = rm; bloc = bi*4 + bj; bg = ga[bj]; }
        }
    }
    int bi = bloc >> 2, bj = bloc & 3;
    int row = 4*i + bi, col = 4*j + bj;
    g_rg[idx] = (bg < 0.1f) ? 0.f : bg;

    int idx2 = row*WWI + col + 1282;
    int col2 = idx2 % WWI;
    int row2 = idx2 / WWI;
    float gx = 2.f * ((float)col2 / 640.f - 0.5f);
    float gy = 2.f * ((float)row2 / 480.f - 0.5f);
    g_ixc[idx] = (gx + 1.f) * 0.5f * 639.f;
    g_iyc[idx] = (gy + 1.f) * 0.5f * 479.f;
}

// ---------------- Kernel 2: grid sample -> bf16 feat ----------------
__global__ void __launch_bounds__(128) k_sample(const float* __restrict__ x) {
    __shared__ float s_x[20*132];
    __shared__ float s_ix[RR][128];
    __shared__ float s_iy[RR][128];
    int tx = threadIdx.x, ty = threadIdx.y;
    int tid = ty*32 + tx;
    int j0 = blockIdx.x * 32, i0 = blockIdx.y * 4, n = blockIdx.z;
    int i = i0 + ty, j = j0 + tx;

    for (int r = 0; r < RR; r++) {
        int gi = ((r*NB + n)*hh + i)*ww + j;
        s_ix[r][tid] = g_ixc[gi];
        s_iy[r][tid] = g_iyc[gi];
    }
    int rb = 4*i0, cb = 4*j0;

    for (int ic = 0; ic < FC; ic++) {
        const float* xp = x + (n*FC + ic) * (HH*WWI);
        __syncthreads();
        for (int t = tid; t < 20*132; t += 128) {
            int lr = t / 132, lc = t % 132;
            int gy = min(rb + lr, HH-1), gx2 = min(cb + lc, WWI-1);
            s_x[t] = xp[gy*WWI + gx2];
        }
        __syncthreads();
        for (int r = 0; r < RR; r++) {
            float ixv = s_ix[r][tid], iyv = s_iy[r][tid];
            float x0f = floorf(ixv), y0f = floorf(iyv);
            float wx = ixv - x0f, wy = iyv - y0f;
            int x0 = (int)x0f, y0 = (int)y0f;
            float f00, f10, f01, f11;
            if (x0 >= cb && x0+1 <= cb+131 && y0 >= rb && y0+1 <= rb+19) {
                const float* s0 = &s_x[(y0-rb)*132 + (x0-cb)];
                f00 = s0[0]; f10 = s0[1]; f01 = s0[132]; f11 = s0[133];
            } else {
                int xa = min(max(x0,   0), WWI-1), xb = min(max(x0+1, 0), WWI-1);
                int ya = min(max(y0,   0), HH-1),  yb = min(max(y0+1, 0), HH-1);
                f00 = xp[ya*WWI+xa]; f10 = xp[ya*WWI+xb];
                f01 = xp[yb*WWI+xa]; f11 = xp[yb*WWI+xb];
            }
            bool okx0 = (x0 >= 0) && (x0 <= WWI-1);
            bool okx1 = (x0+1 <= WWI-1);
            bool oky0 = (y0 >= 0) && (y0 <= HH-1);
            bool oky1 = (y0+1 <= HH-1);
            float w00 = (1.f-wx)*(1.f-wy); if (!(okx0 && oky0)) w00 = 0.f;
            float w10 = wx*(1.f-wy);       if (!(okx1 && oky0)) w10 = 0.f;
            float w01 = (1.f-wx)*wy;       if (!(okx0 && oky1)) w01 = 0.f;
            float w11 = wx*wy;             if (!(okx1 && oky1)) w11 = 0.f;
            float v = f00*w00 + f10*w10 + f01*w01 + f11*w11;
            int z = r*NB + n;
            g_featB[(z*FC + ic)*19200 + i*160 + j] = __float2bfloat16(v);
        }
    }
}

// ---------------- Kernel 3: conv1 via mma.sync (bf16) + sigmoid*d -> g_adT --------
// block 256 = 8 warps; tile 8 rows x 32 cols; warp w owns row w (two m16 groups).
__global__ void __launch_bounds__(256) k_conv1(const float* __restrict__ ba,
                                               const float* __restrict__ dd) {
    __shared__ __align__(16) __nv_bfloat16 s_f[10*34*40];   // [row][col][ic pad40]
    __shared__ __align__(16) __nv_bfloat16 s_w[9*32*32];    // [tap][oc][ic]
    int tid = threadIdx.x, lane = tid & 31, wid = tid >> 5;
    int j0 = blockIdx.x*32, i0 = blockIdx.y*8, z = blockIdx.z;
    int n = z & 3;

    // stage weights (16B chunks): 9*32*32 bf16 = 18432B = 1152 uint4
    {
        const uint4* src = (const uint4*)g_wa_b;
        uint4* dst = (uint4*)s_w;
        for (int t = tid; t < 1152; t += 256) dst[t] = src[t];
    }
    // stage feat with transpose: g_featB[z][ic][i][j] -> s_f[li][lj][ic]
    for (int seg = wid; seg < 320; seg += 8) {
        int li = seg % 10, ic = seg / 10;
        int gi = i0 - 1 + li;
        bool rok = (gi >= 0) && (gi < hh);
        const __nv_bfloat16* src = g_featB + (z*32 + ic)*19200 + gi*160 + (j0 - 1);
        for (int c = lane; c < 34; c += 32) {
            int gj = j0 - 1 + c;
            __nv_bfloat16 v = __float2bfloat16(0.f);
            if (rok && gj >= 0 && gj < ww) v = src[c];
            s_f[(li*34 + c)*40 + ic] = v;
        }
    }
    __syncthreads();

    uint32_t sfb = (uint32_t)__cvta_generic_to_shared(s_f);
    uint32_t swb = (uint32_t)__cvta_generic_to_shared(s_w);
    int r = wid;
    int m = lane & 15;
    int koff = (lane >> 4) * 8;
    uint32_t baseA0 = sfb + (uint32_t)((((r+1)*34 + (m + 1))*40 + koff) * 2);
    int lg = lane >> 3, lr = lane & 7;
    int nrow_off = ((lg & 2) ? 8 : 0) + lr;
    int kboff = (lg & 1) ? 8 : 0;

    float acc[2][4][4];
    #pragma unroll
    for (int s = 0; s < 2; s++)
        #pragma unroll
        for (int nt = 0; nt < 4; nt++)
            #pragma unroll
            for (int q = 0; q < 4; q++) acc[s][nt][q] = 0.f;

    #pragma unroll
    for (int tap = 0; tap < 9; tap++) {
        int dy = tap/3 - 1, dx = tap%3 - 1;
        int offA = (dy*34 + dx)*40*2;
        #pragma unroll
        for (int kc = 0; kc < 2; kc++) {
            uint32_t a0[4], a1[4];
            uint32_t aad = baseA0 + offA + kc*32;
            LDSM_X4(a0[0],a0[1],a0[2],a0[3], aad);
            LDSM_X4(a1[0],a1[1],a1[2],a1[3], aad + 16*40*2);
            #pragma unroll
            for (int p = 0; p < 2; p++) {
                uint32_t bad = swb + (uint32_t)((((tap*32 + p*16 + nrow_off))*32 + kc*16 + kboff) * 2);
                uint32_t b0,b1,b2,b3;
                LDSM_X4(b0,b1,b2,b3, bad);
                MMA_BF16(acc[0][2*p  ], a0[0],a0[1],a0[2],a0[3], b0,b1);
                MMA_BF16(acc[0][2*p+1], a0[0],a0[1],a0[2],a0[3], b2,b3);
                MMA_BF16(acc[1][2*p  ], a1[0],a1[1],a1[2],a1[3], b0,b1);
                MMA_BF16(acc[1][2*p+1], a1[0],a1[1],a1[2],a1[3], b2,b3);
            }
        }
    }

    // epilogue: bias + sigmoid, * d, store bf16 [pos][oc]
    int i = i0 + r;
    #pragma unroll
    for (int s = 0; s < 2; s++) {
        int cbase = s*16 + (lane >> 2);
        #pragma unroll
        for (int nt = 0; nt < 4; nt++) {
            int oc = nt*8 + 2*(lane & 3);
            float b0v = ba[oc], b1v = ba[oc+1];
            #pragma unroll
            for (int half = 0; half < 2; half++) {
                int c = cbase + half*8;
                int j = j0 + c;
                float v0 = acc[s][nt][half*2+0] + b0v;
                float v1 = acc[s][nt][half*2+1] + b1v;
                float att0 = 1.f/(1.f + __expf(-v0));
                float att1 = 1.f/(1.f + __expf(-v1));
                float d0 = dd[((n*DC + oc  )*hh + i)*ww + j];
                float d1 = dd[((n*DC + oc+1)*hh + i)*ww + j];
                __nv_bfloat162 pk;
                pk.x = __float2bfloat16(att0*d0);
                pk.y = __float2bfloat16(att1*d1);
                *reinterpret_cast<__nv_bfloat162*>(
                    &g_adT[(z*19200 + i*160 + j)*32 + oc]) = pk;
            }
        }
    }
}

// ---------------- Kernel 4: conv2 via mma.sync + fused loss ----------------
__global__ void __launch_bounds__(256) k_conv2(const float* __restrict__ bp) {
    __shared__ __align__(16) __nv_bfloat16 s_a[10*34*40];
    __shared__ __align__(16) __nv_bfloat16 s_w2[9*8*32];
    __shared__ float s_rg[10*36];
    __shared__ float s_red[16];
    int tid = threadIdx.x, lane = tid & 31, wid = tid >> 5;
    int j0 = blockIdx.x*32, i0 = blockIdx.y*8, z = blockIdx.z;
    int rr = z >> 2;

    // stage weights: 9*8*32 bf16 = 4608B = 288 uint4
    {
        const uint4* src = (const uint4*)g_wp_b;
        uint4* dst = (uint4*)s_w2;
        for (int t = tid; t < 288; t += 256) dst[t] = src[t];
    }
    for (int t = tid; t < 10*34; t += 256) {
        int lc = t % 34, lrr = t / 34;
        int gi = i0 - 1 + lrr, gj = j0 - 1 + lc;
        float v = 0.f;
        if (gi >= 0 && gi < hh && gj >= 0 && gj < ww) v = g_rg[(z*hh + gi)*ww + gj];
        s_rg[lrr*36 + lc] = v;
    }
    // stage ad: g_adT[z][pos][ic] -> s_a[li][lj][ic]  (16B chunks, no transpose)
    for (int t = tid; t < 10*34*4; t += 256) {
        int chunk = t & 3; int lj = (t >> 2) % 34; int li = t / (4*34);
        int gi = i0 - 1 + li, gj = j0 - 1 + lj;
        uint4 v = make_uint4(0,0,0,0);
        if (gi >= 0 && gi < hh && gj >= 0 && gj < ww)
            v = *reinterpret_cast<const uint4*>(
                &g_adT[(z*19200 + gi*160 + gj)*32 + chunk*8]);
        *reinterpret_cast<uint4*>(&s_a[(li*34 + lj)*40 + chunk*8]) = v;
    }
    __syncthreads();

    uint32_t sab = (uint32_t)__cvta_generic_to_shared(s_a);
    uint32_t swb = (uint32_t)__cvta_generic_to_shared(s_w2);
    int r = wid;
    int m = lane & 15;
    int koff = (lane >> 4) * 8;
    uint32_t baseA0 = sab + (uint32_t)((((r+1)*34 + (m + 1))*40 + koff) * 2);
    int nrow2 = lane & 7;
    int kboff2 = ((lane >> 3) & 1) ? 8 : 0;

    float acc[2][4];
    #pragma unroll
    for (int s = 0; s < 2; s++)
        #pragma unroll
        for (int q = 0; q < 4; q++) acc[s][q] = 0.f;

    #pragma unroll
    for (int tap = 0; tap < 9; tap++) {
        int dy = tap/3 - 1, dx = tap%3 - 1;
        int offA = (dy*34 + dx)*40*2;
        #pragma unroll
        for (int kc = 0; kc < 2; kc++) {
            uint32_t a0[4], a1[4];
            uint32_t aad = baseA0 + offA + kc*32;
            LDSM_X4(a0[0],a0[1],a0[2],a0[3], aad);
            LDSM_X4(a1[0],a1[1],a1[2],a1[3], aad + 16*40*2);
            uint32_t bad = swb + (uint32_t)(((tap*8 + nrow2)*32 + kc*16 + kboff2) * 2);
            uint32_t b0,b1;
            LDSM_X2(b0,b1, bad);
            MMA_BF16(acc[0], a0[0],a0[1],a0[2],a0[3], b0,b1);
            MMA_BF16(acc[1], a1[0],a1[1],a1[2],a1[3], b0,b1);
        }
    }

    // loss epilogue
    float num = 0.f, den = 0.f;
    int ocl = 2*(lane & 3);
    if (ocl < 4) {
        #pragma unroll
        for (int s = 0; s < 2; s++) {
            #pragma unroll
            for (int q = 0; q < 4; q++) {
                int oc = ocl + (q & 1);
                int m2 = (lane >> 2) + ((q >> 1) * 8);
                int c = s*16 + m2;
                float ds = acc[s][q] + bp[oc];
                int ox = (oc >= 1) ? 1 : 0;
                int oy = (oc < 2) ? 1 : ((oc == 2) ? 0 : -1);
                float cen = s_rg[(r+1)*36 + (c+1)];
                float nbv = s_rg[(r+1+ox)*36 + (c+1+oy)];
                float grad = __logf(cen + 1e-6f) - __logf(nbv + 1e-6f);
                float a = fabsf(ds - grad);
                float sl1 = (a < 0.01f) ? (0.5f*a*a/0.01f) : (a - 0.005f);
                if (cen > 0.1f && nbv > 0.1f) { num += sl1; den += 1.f; }
            }
        }
    }
    #pragma unroll
    for (int o = 16; o > 0; o >>= 1) {
        num += __shfl_down_sync(0xffffffffu, num, o);
        den += __shfl_down_sync(0xffffffffu, den, o);
    }
    if (lane == 0) { s_red[wid] = num; s_red[8 + wid] = den; }
    __syncthreads();
    if (tid == 0) {
        float sn = 0.f, sd = 0.f;
        #pragma unroll
        for (int w = 0; w < 8; w++) { sn += s_red[w]; sd += s_red[8+w]; }
        atomicAdd(&g_num[rr], sn);
        atomicAdd(&g_den[rr], sd);
    }
}

__global__ void k_final(float* out) {
    if (threadIdx.x == 0) {
        float tot = 0.f;
        for (int r = 0; r < RR; r++) tot += g_num[r] / g_den[r];
        out[0] = tot / 20.0f;
    }
}

extern "C" void kernel_launch(void* const* d_in, const int* in_sizes, int n_in,
                              void* d_out, int out_size) {
    const float* x    = (const float*)d_in[0];
    const float* d    = (const float*)d_in[1];
    const float* gts  = (const float*)d_in[2];
    const float* rnd  = (const float*)d_in[3];
    const float* Wa   = (const float*)d_in[4];
    const float* ba   = (const float*)d_in[5];
    const float* Wp   = (const float*)d_in[6];
    const float* bp   = (const float*)d_in[7];
    float* out = (float*)d_out;

    k_zero<<<1, 32>>>();
    k_wcvt<<<36, 256>>>(Wa, Wp);
    k_pool<<<(RR*NB*hh*ww + 255)/256, 256>>>(gts, rnd);

    dim3 bs2(32, 4), gs2(ww/32, hh/4, NB);
    k_sample<<<gs2, bs2>>>(x);

    dim3 bs3(256), gs3(ww/32, hh/8, RR*NB);
    k_conv1<<<gs3, bs3>>>(ba, d);

    dim3 bs4(256), gs4(ww/32, hh/8, RR*NB);
    k_conv2<<<gs4, bs4>>>(bp);

    k_final<<<1, 32>>>(out);
}

// round 6
// speedup vs baseline: 2.2079x; 1.3006x over previous
#include <cuda_runtime.h>
#include <cuda_bf16.h>
#include <cuda_fp16.h>
#include <math.h>
#include <stdint.h>

#define RR 20
#define NB 4
#define HH 480
#define WWI 640
#define hh 120
#define ww 160
#define FC 32
#define DC 32

// Scratch (static device globals; no allocations). 16B-aligned: accessed via uint4.
__device__ float g_rg [RR*NB*hh*ww];
__device__ float g_ixc[RR*NB*hh*ww];
__device__ float g_iyc[RR*NB*hh*ww];
__device__ __align__(16) __nv_bfloat16 g_featT[RR*NB*hh*ww*FC];  // [z][pos][ic]  98MB
__device__ __align__(16) __nv_bfloat16 g_adT [RR*NB*hh*ww*DC];   // [z][pos][ic]  98MB
__device__ __align__(16) __nv_bfloat16 g_wa_b[9*32*32];          // [tap][oc][ic]
__device__ __align__(16) __nv_bfloat16 g_wp_b[9*8*32];           // [tap][oc(8,pad)][ic]
__device__ float g_num[RR];
__device__ float g_den[RR];

// ---------------- PTX helpers ----------------
#define LDSM_X4(r0,r1,r2,r3,addr) \
    asm volatile("ldmatrix.sync.aligned.m8n8.x4.shared.b16 {%0,%1,%2,%3}, [%4];" \
        : "=r"(r0),"=r"(r1),"=r"(r2),"=r"(r3) : "r"(addr))

#define LDSM_X2(r0,r1,addr) \
    asm volatile("ldmatrix.sync.aligned.m8n8.x2.shared.b16 {%0,%1}, [%2];" \
        : "=r"(r0),"=r"(r1) : "r"(addr))

#define MMA_BF16(d, a0,a1,a2,a3, b0,b1) \
    asm volatile("mma.sync.aligned.m16n8k16.row.col.f32.bf16.bf16.f32 " \
        "{%0,%1,%2,%3},{%4,%5,%6,%7},{%8,%9},{%0,%1,%2,%3};" \
        : "+f"((d)[0]),"+f"((d)[1]),"+f"((d)[2]),"+f"((d)[3]) \
        : "r"(a0),"r"(a1),"r"(a2),"r"(a3),"r"(b0),"r"(b1))

__global__ void k_zero() {
    int t = threadIdx.x;
    if (t < RR) { g_num[t] = 0.f; g_den[t] = 0.f; }
}

// ---------------- weight convert ----------------
__global__ void k_wcvt(const float* __restrict__ Wa, const float* __restrict__ Wp) {
    int t = blockIdx.x * 256 + threadIdx.x;
    if (t < 9*32*32) {
        int ic = t & 31, oc = (t >> 5) & 31, tap = t >> 10;
        g_wa_b[t] = __float2bfloat16(Wa[(oc*32 + ic)*9 + tap]);
    }
    if (t < 9*8*32) {
        int ic = t & 31, oc = (t >> 5) & 7, tap = t >> 8;
        float v = (oc < 4) ? Wp[(oc*32 + ic)*9 + tap] : 0.f;
        g_wp_b[t] = __float2bfloat16(v);
    }
}

// ---------------- Kernel 1: random pooling + sample coords ----------------
__global__ void k_pool(const float* __restrict__ gts, const float* __restrict__ rnd) {
    int idx = blockIdx.x * blockDim.x + threadIdx.x;
    if (idx >= RR*NB*hh*ww) return;
    int j = idx % ww; int t = idx / ww;
    int i = t % hh;  t /= hh;
    int n = t % NB;  int r = t / NB;

    const float* gp = gts + n * (HH*WWI);
    const float* rp = rnd + (r*NB + n) * (HH*WWI);

    float best = -1.f; int bloc = 0; float bg = 0.f;
    #pragma unroll
    for (int bi = 0; bi < 4; bi++) {
        int off = (4*i + bi)*WWI + 4*j;
        float4 g4 = *reinterpret_cast<const float4*>(gp + off);
        float4 r4 = *reinterpret_cast<const float4*>(rp + off);
        float ga[4] = {g4.x, g4.y, g4.z, g4.w};
        float ra[4] = {r4.x, r4.y, r4.z, r4.w};
        #pragma unroll
        for (int bj = 0; bj < 4; bj++) {
            float rm = (ga[bj] > 0.1f) ? ra[bj] : 0.f;
            if (rm > best) { best = rm; bloc = bi*4 + bj; bg = ga[bj]; }
        }
    }
    int bi = bloc >> 2, bj = bloc & 3;
    int row = 4*i + bi, col = 4*j + bj;
    g_rg[idx] = (bg < 0.1f) ? 0.f : bg;

    int idx2 = row*WWI + col + 1282;
    int col2 = idx2 % WWI;
    int row2 = idx2 / WWI;
    float gx = 2.f * ((float)col2 / 640.f - 0.5f);
    float gy = 2.f * ((float)row2 / 480.f - 0.5f);
    g_ixc[idx] = (gx + 1.f) * 0.5f * 639.f;
    g_iyc[idx] = (gy + 1.f) * 0.5f * 479.f;
}

// ---------------- Kernel 2: grid sample -> bf16 featT [z][pos][ic] ----------------
// block (32,4)=128; output tile 4x32 positions, 8 ic per block; grid (5, 30, 16).
// Coords precomputed to registers (packed uint2 per r); output accumulated in smem
// and flushed as uint4 (8 ic contiguous).
__global__ void __launch_bounds__(128) k_sample(const float* __restrict__ x) {
    __shared__ __nv_bfloat16 s_x[20*132];                  // bf16 x tile
    __shared__ __align__(16) __nv_bfloat16 s_t[20][128][8];
    int tx = threadIdx.x, ty = threadIdx.y;
    int tid = ty*32 + tx;
    int j0 = blockIdx.x * 32, i0 = blockIdx.y * 4;
    int zb = blockIdx.z; int n = zb & 3, icg = zb >> 2;
    int i = i0 + ty, j = j0 + tx;
    int rb = 4*i0, cb = 4*j0;

    // phase A: pack per-r coords into registers
    uint2 lc[RR];
    #pragma unroll
    for (int r = 0; r < RR; r++) {
        int gi = ((r*NB + n)*hh + i)*ww + j;
        float ixv = g_ixc[gi], iyv = g_iyc[gi];
        float x0f = floorf(ixv), y0f = floorf(iyv);
        int x0 = (int)x0f, y0 = (int)y0f;
        float wx = ixv - x0f, wy = iyv - y0f;
        unsigned m0 = (y0 <= HH-1) ? 1u : 0u;     // y0 >= 0 always
        unsigned m1 = (y0+1 <= HH-1) ? 1u : 0u;
        unsigned off;
        if (x0 >= cb && x0+1 <= cb+131 && y0 >= rb && y0+1 <= rb+19)
            off = (unsigned)((y0-rb)*132 + (x0-cb));   // <= 2639 < 0x3FFF
        else off = 0x3FFFu;                             // fallback sentinel
        unsigned w0 = off | (m0 << 14) | (m1 << 15)
                    | ((unsigned)__half_as_ushort(__float2half_rn(wx)) << 16);
        unsigned w1 = (unsigned)__half_as_ushort(__float2half_rn(wy));
        lc[r] = make_uint2(w0, w1);
    }

    // phase B: per-ic tile stage + 20 samples
    for (int ic8 = 0; ic8 < 8; ic8++) {
        int icc = icg*8 + ic8;
        const float* xp = x + (n*FC + icc) * (HH*WWI);
        __syncthreads();
        for (int t = tid; t < 20*132; t += 128) {
            int lr = t / 132, lcx = t % 132;
            int gy = min(rb + lr, HH-1), gx2 = min(cb + lcx, WWI-1);
            s_x[t] = __float2bfloat16(xp[gy*WWI + gx2]);
        }
        __syncthreads();
        #pragma unroll
        for (int r = 0; r < RR; r++) {
            unsigned w0 = lc[r].x, w1 = lc[r].y;
            unsigned off = w0 & 0x3FFFu;
            float v;
            if (off != 0x3FFFu) {
                float wx = __half2float(__ushort_as_half((unsigned short)(w0 >> 16)));
                float wy = __half2float(__ushort_as_half((unsigned short)(w1 & 0xFFFFu)));
                float m0 = (w0 & (1u<<14)) ? 1.f : 0.f;
                float m1 = (w0 & (1u<<15)) ? 1.f : 0.f;
                const __nv_bfloat16* s0 = &s_x[off];
                float f00 = __bfloat162float(s0[0]);
                float f10 = __bfloat162float(s0[1]);
                float f01 = __bfloat162float(s0[132]);
                float f11 = __bfloat162float(s0[133]);
                float wy0 = (1.f - wy) * m0, wy1 = wy * m1;
                v = (f00 + (f10 - f00)*wx) * wy0 + (f01 + (f11 - f01)*wx) * wy1;
            } else {
                // rare: column-wrap / off-tile — full global path in f32
                int gi = ((r*NB + n)*hh + i)*ww + j;
                float ixv = g_ixc[gi], iyv = g_iyc[gi];
                float x0f = floorf(ixv), y0f = floorf(iyv);
                float fwx = ixv - x0f, fwy = iyv - y0f;
                int X0 = (int)x0f, Y0 = (int)y0f;
                int xa = min(max(X0,   0), WWI-1), xb = min(max(X0+1, 0), WWI-1);
                int ya = min(max(Y0,   0), HH-1),  yb = min(max(Y0+1, 0), HH-1);
                float f00 = xp[ya*WWI+xa], f10 = xp[ya*WWI+xb];
                float f01 = xp[yb*WWI+xa], f11 = xp[yb*WWI+xb];
                bool okx0 = (X0 >= 0) && (X0 <= WWI-1);
                bool okx1 = (X0+1 <= WWI-1);
                bool oky0 = (Y0 >= 0) && (Y0 <= HH-1);
                bool oky1 = (Y0+1 <= HH-1);
                float w00 = (okx0 && oky0) ? (1.f-fwx)*(1.f-fwy) : 0.f;
                float w10 = (okx1 && oky0) ? fwx*(1.f-fwy) : 0.f;
                float w01 = (okx0 && oky1) ? (1.f-fwx)*fwy : 0.f;
                float w11 = (okx1 && oky1) ? fwx*fwy : 0.f;
                v = f00*w00 + f10*w10 + f01*w01 + f11*w11;
            }
            s_t[r][tid][ic8] = __float2bfloat16(v);
        }
    }

    // phase C: flush own data (no sync needed)
    #pragma unroll
    for (int r = 0; r < RR; r++) {
        uint4 v = *reinterpret_cast<const uint4*>(&s_t[r][tid][0]);
        int z = r*NB + n;
        *reinterpret_cast<uint4*>(
            &g_featT[(z*19200 + i*160 + j)*32 + icg*8]) = v;
    }
}

// ---------------- Kernel 3: conv1 via mma.sync (bf16) + sigmoid*d -> g_adT --------
// block 256 = 8 warps; tile 8 rows x 32 cols; warp w owns row w (two m16 groups).
__global__ void __launch_bounds__(256) k_conv1(const float* __restrict__ ba,
                                               const float* __restrict__ dd) {
    __shared__ __align__(16) __nv_bfloat16 s_f[10*34*40];   // [row][col][ic pad40]
    __shared__ __align__(16) __nv_bfloat16 s_w[9*32*32];    // [tap][oc][ic]
    int tid = threadIdx.x, lane = tid & 31, wid = tid >> 5;
    int j0 = blockIdx.x*32, i0 = blockIdx.y*8, z = blockIdx.z;
    int n = z & 3;

    // stage weights (16B chunks): 9*32*32 bf16 = 18432B = 1152 uint4
    {
        const uint4* src = (const uint4*)g_wa_b;
        uint4* dst = (uint4*)s_w;
        for (int t = tid; t < 1152; t += 256) dst[t] = src[t];
    }
    // stage feat from g_featT[z][pos][ic] (uint4 chunks, no transpose)
    for (int t = tid; t < 10*34*4; t += 256) {
        int chunk = t & 3; int lj = (t >> 2) % 34; int li = t / 136;
        int gi = i0 - 1 + li, gj = j0 - 1 + lj;
        uint4 v = make_uint4(0,0,0,0);
        if (gi >= 0 && gi < hh && gj >= 0 && gj < ww)
            v = *reinterpret_cast<const uint4*>(
                &g_featT[(z*19200 + gi*160 + gj)*32 + chunk*8]);
        *reinterpret_cast<uint4*>(&s_f[(li*34 + lj)*40 + chunk*8]) = v;
    }
    __syncthreads();

    uint32_t sfb = (uint32_t)__cvta_generic_to_shared(s_f);
    uint32_t swb = (uint32_t)__cvta_generic_to_shared(s_w);
    int r = wid;
    int m = lane & 15;
    int koff = (lane >> 4) * 8;
    uint32_t baseA0 = sfb + (uint32_t)((((r+1)*34 + (m + 1))*40 + koff) * 2);
    int lg = lane >> 3, lr = lane & 7;
    int nrow_off = ((lg & 2) ? 8 : 0) + lr;
    int kboff = (lg & 1) ? 8 : 0;

    float acc[2][4][4];
    #pragma unroll
    for (int s = 0; s < 2; s++)
        #pragma unroll
        for (int nt = 0; nt < 4; nt++)
            #pragma unroll
            for (int q = 0; q < 4; q++) acc[s][nt][q] = 0.f;

    #pragma unroll
    for (int tap = 0; tap < 9; tap++) {
        int dy = tap/3 - 1, dx = tap%3 - 1;
        int offA = (dy*34 + dx)*40*2;
        #pragma unroll
        for (int kc = 0; kc < 2; kc++) {
            uint32_t a0[4], a1[4];
            uint32_t aad = baseA0 + offA + kc*32;
            LDSM_X4(a0[0],a0[1],a0[2],a0[3], aad);
            LDSM_X4(a1[0],a1[1],a1[2],a1[3], aad + 16*40*2);
            #pragma unroll
            for (int p = 0; p < 2; p++) {
                uint32_t bad = swb + (uint32_t)((((tap*32 + p*16 + nrow_off))*32 + kc*16 + kboff) * 2);
                uint32_t b0,b1,b2,b3;
                LDSM_X4(b0,b1,b2,b3, bad);
                MMA_BF16(acc[0][2*p  ], a0[0],a0[1],a0[2],a0[3], b0,b1);
                MMA_BF16(acc[0][2*p+1], a0[0],a0[1],a0[2],a0[3], b2,b3);
                MMA_BF16(acc[1][2*p  ], a1[0],a1[1],a1[2],a1[3], b0,b1);
                MMA_BF16(acc[1][2*p+1], a1[0],a1[1],a1[2],a1[3], b2,b3);
            }
        }
    }

    // epilogue: bias + sigmoid, * d, store bf16 [pos][oc]
    int i = i0 + r;
    #pragma unroll
    for (int s = 0; s < 2; s++) {
        int cbase = s*16 + (lane >> 2);
        #pragma unroll
        for (int nt = 0; nt < 4; nt++) {
            int oc = nt*8 + 2*(lane & 3);
            float b0v = ba[oc], b1v = ba[oc+1];
            #pragma unroll
            for (int half = 0; half < 2; half++) {
                int c = cbase + half*8;
                int j = j0 + c;
                float v0 = acc[s][nt][half*2+0] + b0v;
                float v1 = acc[s][nt][half*2+1] + b1v;
                float att0 = 1.f/(1.f + __expf(-v0));
                float att1 = 1.f/(1.f + __expf(-v1));
                float d0 = dd[((n*DC + oc  )*hh + i)*ww + j];
                float d1 = dd[((n*DC + oc+1)*hh + i)*ww + j];
                __nv_bfloat162 pk;
                pk.x = __float2bfloat16(att0*d0);
                pk.y = __float2bfloat16(att1*d1);
                *reinterpret_cast<__nv_bfloat162*>(
                    &g_adT[(z*19200 + i*160 + j)*32 + oc]) = pk;
            }
        }
    }
}

// ---------------- Kernel 4: conv2 via mma.sync + fused loss ----------------
__global__ void __launch_bounds__(256) k_conv2(const float* __restrict__ bp) {
    __shared__ __align__(16) __nv_bfloat16 s_a[10*34*40];
    __shared__ __align__(16) __nv_bfloat16 s_w2[9*8*32];
    __shared__ float s_rg[10*36];
    __shared__ float s_red[16];
    int tid = threadIdx.x, lane = tid & 31, wid = tid >> 5;
    int j0 = blockIdx.x*32, i0 = blockIdx.y*8, z = blockIdx.z;
    int rr = z >> 2;

    // stage weights: 9*8*32 bf16 = 4608B = 288 uint4
    {
        const uint4* src = (const uint4*)g_wp_b;
        uint4* dst = (uint4*)s_w2;
        for (int t = tid; t < 288; t += 256) dst[t] = src[t];
    }
    for (int t = tid; t < 10*34; t += 256) {
        int lcx = t % 34, lrr = t / 34;
        int gi = i0 - 1 + lrr, gj = j0 - 1 + lcx;
        float v = 0.f;
        if (gi >= 0 && gi < hh && gj >= 0 && gj < ww) v = g_rg[(z*hh + gi)*ww + gj];
        s_rg[lrr*36 + lcx] = v;
    }
    // stage ad: g_adT[z][pos][ic] -> s_a[li][lj][ic]  (16B chunks)
    for (int t = tid; t < 10*34*4; t += 256) {
        int chunk = t & 3; int lj = (t >> 2) % 34; int li = t / 136;
        int gi = i0 - 1 + li, gj = j0 - 1 + lj;
        uint4 v = make_uint4(0,0,0,0);
        if (gi >= 0 && gi < hh && gj >= 0 && gj < ww)
            v = *reinterpret_cast<const uint4*>(
                &g_adT[(z*19200 + gi*160 + gj)*32 + chunk*8]);
        *reinterpret_cast<uint4*>(&s_a[(li*34 + lj)*40 + chunk*8]) = v;
    }
    __syncthreads();

    uint32_t sab = (uint32_t)__cvta_generic_to_shared(s_a);
    uint32_t swb = (uint32_t)__cvta_generic_to_shared(s_w2);
    int r = wid;
    int m = lane & 15;
    int koff = (lane >> 4) * 8;
    uint32_t baseA0 = sab + (uint32_t)((((r+1)*34 + (m + 1))*40 + koff) * 2);
    int nrow2 = lane & 7;
    int kboff2 = ((lane >> 3) & 1) ? 8 : 0;

    float acc[2][4];
    #pragma unroll
    for (int s = 0; s < 2; s++)
        #pragma unroll
        for (int q = 0; q < 4; q++) acc[s][q] = 0.f;

    #pragma unroll
    for (int tap = 0; tap < 9; tap++) {
        int dy = tap/3 - 1, dx = tap%3 - 1;
        int offA = (dy*34 + dx)*40*2;
        #pragma unroll
        for (int kc = 0; kc < 2; kc++) {
            uint32_t a0[4], a1[4];
            uint32_t aad = baseA0 + offA + kc*32;
            LDSM_X4(a0[0],a0[1],a0[2],a0[3], aad);
            LDSM_X4(a1[0],a1[1],a1[2],a1[3], aad + 16*40*2);
            uint32_t bad = swb + (uint32_t)(((tap*8 + nrow2)*32 + kc*16 + kboff2) * 2);
            uint32_t b0,b1;
            LDSM_X2(b0,b1, bad);
            MMA_BF16(acc[0], a0[0],a0[1],a0[2],a0[3], b0,b1);
            MMA_BF16(acc[1], a1[0],a1[1],a1[2],a1[3], b0,b1);
        }
    }

    // loss epilogue
    float num = 0.f, den = 0.f;
    int ocl = 2*(lane & 3);
    if (ocl < 4) {
        #pragma unroll
        for (int s = 0; s < 2; s++) {
            #pragma unroll
            for (int q = 0; q < 4; q++) {
                int oc = ocl + (q & 1);
                int m2 = (lane >> 2) + ((q >> 1) * 8);
                int c = s*16 + m2;
                float ds = acc[s][q] + bp[oc];
                int ox = (oc >= 1) ? 1 : 0;
                int oy = (oc < 2) ? 1 : ((oc == 2) ? 0 : -1);
                float cen = s_rg[(r+1)*36 + (c+1)];
                float nbv = s_rg[(r+1+ox)*36 + (c+1+oy)];
                float grad = __logf(cen + 1e-6f) - __logf(nbv + 1e-6f);
                float a = fabsf(ds - grad);
                float sl1 = (a < 0.01f) ? (0.5f*a*a/0.01f) : (a - 0.005f);
                if (cen > 0.1f && nbv > 0.1f) { num += sl1; den += 1.f; }
            }
        }
    }
    #pragma unroll
    for (int o = 16; o > 0; o >>= 1) {
        num += __shfl_down_sync(0xffffffffu, num, o);
        den += __shfl_down_sync(0xffffffffu, den, o);
    }
    if (lane == 0) { s_red[wid] = num; s_red[8 + wid] = den; }
    __syncthreads();
    if (tid == 0) {
        float sn = 0.f, sd = 0.f;
        #pragma unroll
        for (int w = 0; w < 8; w++) { sn += s_red[w]; sd += s_red[8+w]; }
        atomicAdd(&g_num[rr], sn);
        atomicAdd(&g_den[rr], sd);
    }
}

__global__ void k_final(float* out) {
    if (threadIdx.x == 0) {
        float tot = 0.f;
        for (int r = 0; r < RR; r++) tot += g_num[r] / g_den[r];
        out[0] = tot / 20.0f;
    }
}

extern "C" void kernel_launch(void* const* d_in, const int* in_sizes, int n_in,
                              void* d_out, int out_size) {
    const float* x    = (const float*)d_in[0];
    const float* d    = (const float*)d_in[1];
    const float* gts  = (const float*)d_in[2];
    const float* rnd  = (const float*)d_in[3];
    const float* Wa   = (const float*)d_in[4];
    const float* ba   = (const float*)d_in[5];
    const float* Wp   = (const float*)d_in[6];
    const float* bp   = (const float*)d_in[7];
    float* out = (float*)d_out;

    k_zero<<<1, 32>>>();
    k_wcvt<<<36, 256>>>(Wa, Wp);
    k_pool<<<(RR*NB*hh*ww + 255)/256, 256>>>(gts, rnd);

    dim3 bs2(32, 4), gs2(ww/32, hh/4, NB*4);
    k_sample<<<gs2, bs2>>>(x);

    dim3 bs3(256), gs3(ww/32, hh/8, RR*NB);
    k_conv1<<<gs3, bs3>>>(ba, d);

    dim3 bs4(256), gs4(ww/32, hh/8, RR*NB);
    k_conv2<<<gs4, bs4>>>(bp);

    k_final<<<1, 32>>>(out);
}

// round 7
// speedup vs baseline: 2.8780x; 1.3035x over previous
#include <cuda_runtime.h>
#include <cuda_bf16.h>
#include <cuda_fp16.h>
#include <math.h>
#include <stdint.h>

#define RR 20
#define NB 4
#define HH 480
#define WWI 640
#define hh 120
#define ww 160
#define FC 32
#define DC 32
#define HWSZ (HH*WWI)

// Scratch (static device globals; no allocations). 16B-aligned: accessed via uint4.
__device__ float g_rg [RR*NB*hh*ww];
__device__ float g_ixc[RR*NB*hh*ww];
__device__ float g_iyc[RR*NB*hh*ww];
__device__ __align__(16) __nv_bfloat16 g_featT[RR*NB*hh*ww*FC];  // [z][pos][ic]  98MB
__device__ __align__(16) __nv_bfloat16 g_adT [RR*NB*hh*ww*DC];   // [z][pos][ic]  98MB
__device__ __align__(16) __nv_bfloat16 g_wa_b[9*32*32];          // [tap][oc][ic]
__device__ __align__(16) __nv_bfloat16 g_wp_b[9*8*32];           // [tap][oc(8,pad)][ic]
__device__ float g_num[RR];
__device__ float g_den[RR];

// ---------------- PTX helpers ----------------
#define LDSM_X4(r0,r1,r2,r3,addr) \
    asm volatile("ldmatrix.sync.aligned.m8n8.x4.shared.b16 {%0,%1,%2,%3}, [%4];" \
        : "=r"(r0),"=r"(r1),"=r"(r2),"=r"(r3) : "r"(addr))

#define LDSM_X2(r0,r1,addr) \
    asm volatile("ldmatrix.sync.aligned.m8n8.x2.shared.b16 {%0,%1}, [%2];" \
        : "=r"(r0),"=r"(r1) : "r"(addr))

#define MMA_BF16(d, a0,a1,a2,a3, b0,b1) \
    asm volatile("mma.sync.aligned.m16n8k16.row.col.f32.bf16.bf16.f32 " \
        "{%0,%1,%2,%3},{%4,%5,%6,%7},{%8,%9},{%0,%1,%2,%3};" \
        : "+f"((d)[0]),"+f"((d)[1]),"+f"((d)[2]),"+f"((d)[3]) \
        : "r"(a0),"r"(a1),"r"(a2),"r"(a3),"r"(b0),"r"(b1))

__global__ void k_zero() {
    int t = threadIdx.x;
    if (t < RR) { g_num[t] = 0.f; g_den[t] = 0.f; }
}

// ---------------- weight convert ----------------
__global__ void k_wcvt(const float* __restrict__ Wa, const float* __restrict__ Wp) {
    int t = blockIdx.x * 256 + threadIdx.x;
    if (t < 9*32*32) {
        int ic = t & 31, oc = (t >> 5) & 31, tap = t >> 10;
        g_wa_b[t] = __float2bfloat16(Wa[(oc*32 + ic)*9 + tap]);
    }
    if (t < 9*8*32) {
        int ic = t & 31, oc = (t >> 5) & 7, tap = t >> 8;
        float v = (oc < 4) ? Wp[(oc*32 + ic)*9 + tap] : 0.f;
        g_wp_b[t] = __float2bfloat16(v);
    }
}

// ---------------- Kernel 1: random pooling + sample coords ----------------
__global__ void k_pool(const float* __restrict__ gts, const float* __restrict__ rnd) {
    int idx = blockIdx.x * blockDim.x + threadIdx.x;
    if (idx >= RR*NB*hh*ww) return;
    int j = idx % ww; int t = idx / ww;
    int i = t % hh;  t /= hh;
    int n = t % NB;  int r = t / NB;

    const float* gp = gts + n * HWSZ;
    const float* rp = rnd + (r*NB + n) * HWSZ;

    float best = -1.f; int bloc = 0; float bg = 0.f;
    #pragma unroll
    for (int bi = 0; bi < 4; bi++) {
        int off = (4*i + bi)*WWI + 4*j;
        float4 g4 = *reinterpret_cast<const float4*>(gp + off);
        float4 r4 = *reinterpret_cast<const float4*>(rp + off);
        float ga[4] = {g4.x, g4.y, g4.z, g4.w};
        float ra[4] = {r4.x, r4.y, r4.z, r4.w};
        #pragma unroll
        for (int bj = 0; bj < 4; bj++) {
            float rm = (ga[bj] > 0.1f) ? ra[bj] : 0.f;
            if (rm > best) { best = rm; bloc = bi*4 + bj; bg = ga[bj]; }
        }
    }
    int bi = bloc >> 2, bj = bloc & 3;
    int row = 4*i + bi, col = 4*j + bj;
    g_rg[idx] = (bg < 0.1f) ? 0.f : bg;

    int idx2 = row*WWI + col + 1282;
    int col2 = idx2 % WWI;
    int row2 = idx2 / WWI;
    float gx = 2.f * ((float)col2 / 640.f - 0.5f);
    float gy = 2.f * ((float)row2 / 480.f - 0.5f);
    g_ixc[idx] = (gx + 1.f) * 0.5f * 639.f;
    g_iyc[idx] = (gy + 1.f) * 0.5f * 479.f;
}

// ---------------- Kernel 2: grid sample -> bf16 featT [z][pos][ic] ----------------
// block (32,4)=128; output tile 4x32 positions, 8 ic per block; grid (5, 30, 16).
// x tile staged interleaved [pos][ic8] bf16; per (r,thread): decode once,
// 4x LDS.128 corners, bf16x2 lerp, STG.128 direct to g_featT.
__global__ void __launch_bounds__(128) k_sample(const float* __restrict__ x) {
    __shared__ __align__(16) __nv_bfloat16 s_xi[2640*8];   // [pos(20x132)][ic8] 42240B
    int tx = threadIdx.x, ty = threadIdx.y;
    int tid = ty*32 + tx;
    int j0 = blockIdx.x * 32, i0 = blockIdx.y * 4;
    int zb = blockIdx.z; int n = zb & 3, icg = zb >> 2;
    int i = i0 + ty, j = j0 + tx;
    int rb = 4*i0, cb = 4*j0;

    // phase A: pack per-r coords into registers
    uint2 lc[RR];
    #pragma unroll
    for (int r = 0; r < RR; r++) {
        int gi = ((r*NB + n)*hh + i)*ww + j;
        float ixv = g_ixc[gi], iyv = g_iyc[gi];
        float x0f = floorf(ixv), y0f = floorf(iyv);
        int x0 = (int)x0f, y0 = (int)y0f;
        float wx = ixv - x0f, wy = iyv - y0f;
        unsigned m0 = (y0 <= HH-1) ? 1u : 0u;     // y0 >= 0 always
        unsigned m1 = (y0+1 <= HH-1) ? 1u : 0u;
        unsigned off;
        if (x0 >= cb && x0+1 <= cb+131 && y0 >= rb && y0+1 <= rb+19)
            off = (unsigned)((y0-rb)*132 + (x0-cb));   // <= 2506 < 0x3FFF
        else off = 0x3FFFu;                             // fallback sentinel
        unsigned w0 = off | (m0 << 14) | (m1 << 15)
                    | ((unsigned)__half_as_ushort(__float2half_rn(wx)) << 16);
        unsigned w1 = (unsigned)__half_as_ushort(__float2half_rn(wy));
        lc[r] = make_uint2(w0, w1);
    }

    // phase B: stage all 8 channels interleaved
    const float* xbase = x + (n*FC + icg*8) * HWSZ;
    for (int t = tid; t < 2640; t += 128) {
        int lr = t / 132, lcx = t - lr*132;
        int gy = min(rb + lr, HH-1), gx2 = min(cb + lcx, WWI-1);
        const float* p = xbase + gy*WWI + gx2;
        #pragma unroll
        for (int c = 0; c < 8; c += 2) {
            __nv_bfloat162 pk;
            pk.x = __float2bfloat16(p[c*HWSZ]);
            pk.y = __float2bfloat16(p[(c+1)*HWSZ]);
            *reinterpret_cast<__nv_bfloat162*>(&s_xi[t*8 + c]) = pk;
        }
    }
    __syncthreads();

    // phase C: 20 samples, vectorized over 8 ic
    const uint4* sp = reinterpret_cast<const uint4*>(s_xi);
    unsigned fbmask = 0;
    #pragma unroll
    for (int r = 0; r < RR; r++) {
        unsigned w0 = lc[r].x, w1 = lc[r].y;
        unsigned off = w0 & 0x3FFFu;
        if (off == 0x3FFFu) { fbmask |= (1u << r); continue; }
        float wx = __half2float(__ushort_as_half((unsigned short)(w0 >> 16)));
        float wy = __half2float(__ushort_as_half((unsigned short)(w1 & 0xFFFFu)));
        float m0 = (w0 & (1u<<14)) ? 1.f : 0.f;
        float m1 = (w0 & (1u<<15)) ? 1.f : 0.f;
        float wy0 = (1.f - wy) * m0, wy1 = wy * m1;
        __nv_bfloat162 W00 = __float2bfloat162_rn((1.f - wx) * wy0);
        __nv_bfloat162 W10 = __float2bfloat162_rn(wx * wy0);
        __nv_bfloat162 W01 = __float2bfloat162_rn((1.f - wx) * wy1);
        __nv_bfloat162 W11 = __float2bfloat162_rn(wx * wy1);
        uint4 q00 = sp[off], q10 = sp[off+1], q01 = sp[off+132], q11 = sp[off+133];
        const __nv_bfloat162* a00 = reinterpret_cast<const __nv_bfloat162*>(&q00);
        const __nv_bfloat162* a10 = reinterpret_cast<const __nv_bfloat162*>(&q10);
        const __nv_bfloat162* a01 = reinterpret_cast<const __nv_bfloat162*>(&q01);
        const __nv_bfloat162* a11 = reinterpret_cast<const __nv_bfloat162*>(&q11);
        uint4 outv;
        __nv_bfloat162* o = reinterpret_cast<__nv_bfloat162*>(&outv);
        #pragma unroll
        for (int p4 = 0; p4 < 4; p4++)
            o[p4] = __hfma2(a00[p4], W00,
                     __hfma2(a10[p4], W10,
                      __hfma2(a01[p4], W01, __hmul2(a11[p4], W11))));
        int z = r*NB + n;
        *reinterpret_cast<uint4*>(
            &g_featT[(z*19200 + i*160 + j)*32 + icg*8]) = outv;
    }

    // rare fallback (column-wrap): full recompute from global, f32
    while (fbmask) {
        int r = __ffs(fbmask) - 1;
        fbmask &= fbmask - 1;
        int gi = ((r*NB + n)*hh + i)*ww + j;
        float ixv = g_ixc[gi], iyv = g_iyc[gi];
        float x0f = floorf(ixv), y0f = floorf(iyv);
        float fwx = ixv - x0f, fwy = iyv - y0f;
        int X0 = (int)x0f, Y0 = (int)y0f;
        int xa = min(max(X0,   0), WWI-1), xb = min(max(X0+1, 0), WWI-1);
        int ya = min(max(Y0,   0), HH-1),  yb = min(max(Y0+1, 0), HH-1);
        bool okx0 = (X0 >= 0) && (X0 <= WWI-1);
        bool okx1 = (X0+1 <= WWI-1);
        bool oky0 = (Y0 >= 0) && (Y0 <= HH-1);
        bool oky1 = (Y0+1 <= HH-1);
        float w00 = (okx0 && oky0) ? (1.f-fwx)*(1.f-fwy) : 0.f;
        float w10 = (okx1 && oky0) ? fwx*(1.f-fwy) : 0.f;
        float w01 = (okx0 && oky1) ? (1.f-fwx)*fwy : 0.f;
        float w11 = (okx1 && oky1) ? fwx*fwy : 0.f;
        uint4 outv;
        __nv_bfloat16* o = reinterpret_cast<__nv_bfloat16*>(&outv);
        #pragma unroll
        for (int c = 0; c < 8; c++) {
            const float* xp = xbase + c*HWSZ;
            float v = xp[ya*WWI+xa]*w00 + xp[ya*WWI+xb]*w10
                    + xp[yb*WWI+xa]*w01 + xp[yb*WWI+xb]*w11;
            o[c] = __float2bfloat16(v);
        }
        int z = r*NB + n;
        *reinterpret_cast<uint4*>(
            &g_featT[(z*19200 + i*160 + j)*32 + icg*8]) = outv;
    }
}

// ---------------- Kernel 3: conv1 via mma.sync (bf16) + sigmoid*d -> g_adT --------
// block 256 = 8 warps; tile 8 rows x 32 cols; warp w owns row w (two m16 groups).
__global__ void __launch_bounds__(256) k_conv1(const float* __restrict__ ba,
                                               const float* __restrict__ dd) {
    __shared__ __align__(16) __nv_bfloat16 s_f[10*34*40];   // [row][col][ic pad40]
    __shared__ __align__(16) __nv_bfloat16 s_w[9*32*32];    // [tap][oc][ic]
    int tid = threadIdx.x, lane = tid & 31, wid = tid >> 5;
    int j0 = blockIdx.x*32, i0 = blockIdx.y*8, z = blockIdx.z;
    int n = z & 3;

    // stage weights (16B chunks): 9*32*32 bf16 = 18432B = 1152 uint4
    {
        const uint4* src = (const uint4*)g_wa_b;
        uint4* dst = (uint4*)s_w;
        for (int t = tid; t < 1152; t += 256) dst[t] = src[t];
    }
    // stage feat from g_featT[z][pos][ic] (uint4 chunks, no transpose)
    for (int t = tid; t < 10*34*4; t += 256) {
        int chunk = t & 3; int lj = (t >> 2) % 34; int li = t / 136;
        int gi = i0 - 1 + li, gj = j0 - 1 + lj;
        uint4 v = make_uint4(0,0,0,0);
        if (gi >= 0 && gi < hh && gj >= 0 && gj < ww)
            v = *reinterpret_cast<const uint4*>(
                &g_featT[(z*19200 + gi*160 + gj)*32 + chunk*8]);
        *reinterpret_cast<uint4*>(&s_f[(li*34 + lj)*40 + chunk*8]) = v;
    }
    __syncthreads();

    uint32_t sfb = (uint32_t)__cvta_generic_to_shared(s_f);
    uint32_t swb = (uint32_t)__cvta_generic_to_shared(s_w);
    int r = wid;
    int m = lane & 15;
    int koff = (lane >> 4) * 8;
    uint32_t baseA0 = sfb + (uint32_t)((((r+1)*34 + (m + 1))*40 + koff) * 2);
    int lg = lane >> 3, lr = lane & 7;
    int nrow_off = ((lg & 2) ? 8 : 0) + lr;
    int kboff = (lg & 1) ? 8 : 0;

    float acc[2][4][4];
    #pragma unroll
    for (int s = 0; s < 2; s++)
        #pragma unroll
        for (int nt = 0; nt < 4; nt++)
            #pragma unroll
            for (int q = 0; q < 4; q++) acc[s][nt][q] = 0.f;

    #pragma unroll
    for (int tap = 0; tap < 9; tap++) {
        int dy = tap/3 - 1, dx = tap%3 - 1;
        int offA = (dy*34 + dx)*40*2;
        #pragma unroll
        for (int kc = 0; kc < 2; kc++) {
            uint32_t a0[4], a1[4];
            uint32_t aad = baseA0 + offA + kc*32;
            LDSM_X4(a0[0],a0[1],a0[2],a0[3], aad);
            LDSM_X4(a1[0],a1[1],a1[2],a1[3], aad + 16*40*2);
            #pragma unroll
            for (int p = 0; p < 2; p++) {
                uint32_t bad = swb + (uint32_t)((((tap*32 + p*16 + nrow_off))*32 + kc*16 + kboff) * 2);
                uint32_t b0,b1,b2,b3;
                LDSM_X4(b0,b1,b2,b3, bad);
                MMA_BF16(acc[0][2*p  ], a0[0],a0[1],a0[2],a0[3], b0,b1);
                MMA_BF16(acc[0][2*p+1], a0[0],a0[1],a0[2],a0[3], b2,b3);
                MMA_BF16(acc[1][2*p  ], a1[0],a1[1],a1[2],a1[3], b0,b1);
                MMA_BF16(acc[1][2*p+1], a1[0],a1[1],a1[2],a1[3], b2,b3);
            }
        }
    }

    // epilogue: bias + sigmoid, * d, store bf16 [pos][oc]
    int i = i0 + r;
    #pragma unroll
    for (int s = 0; s < 2; s++) {
        int cbase = s*16 + (lane >> 2);
        #pragma unroll
        for (int nt = 0; nt < 4; nt++) {
            int oc = nt*8 + 2*(lane & 3);
            float b0v = ba[oc], b1v = ba[oc+1];
            #pragma unroll
            for (int half = 0; half < 2; half++) {
                int c = cbase + half*8;
                int j = j0 + c;
                float v0 = acc[s][nt][half*2+0] + b0v;
                float v1 = acc[s][nt][half*2+1] + b1v;
                float att0 = 1.f/(1.f + __expf(-v0));
                float att1 = 1.f/(1.f + __expf(-v1));
                float d0 = dd[((n*DC + oc  )*hh + i)*ww + j];
                float d1 = dd[((n*DC + oc+1)*hh + i)*ww + j];
                __nv_bfloat162 pk;
                pk.x = __float2bfloat16(att0*d0);
                pk.y = __float2bfloat16(att1*d1);
                *reinterpret_cast<__nv_bfloat162*>(
                    &g_adT[(z*19200 + i*160 + j)*32 + oc]) = pk;
            }
        }
    }
}

// ---------------- Kernel 4: conv2 via mma.sync + fused loss ----------------
__global__ void __launch_bounds__(256) k_conv2(const float* __restrict__ bp) {
    __shared__ __align__(16) __nv_bfloat16 s_a[10*34*40];
    __shared__ __align__(16) __nv_bfloat16 s_w2[9*8*32];
    __shared__ float s_rg[10*36];
    __shared__ float s_red[16];
    int tid = threadIdx.x, lane = tid & 31, wid = tid >> 5;
    int j0 = blockIdx.x*32, i0 = blockIdx.y*8, z = blockIdx.z;
    int rr = z >> 2;

    // stage weights: 9*8*32 bf16 = 4608B = 288 uint4
    {
        const uint4* src = (const uint4*)g_wp_b;
        uint4* dst = (uint4*)s_w2;
        for (int t = tid; t < 288; t += 256) dst[t] = src[t];
    }
    for (int t = tid; t < 10*34; t += 256) {
        int lcx = t % 34, lrr = t / 34;
        int gi = i0 - 1 + lrr, gj = j0 - 1 + lcx;
        float v = 0.f;
        if (gi >= 0 && gi < hh && gj >= 0 && gj < ww) v = g_rg[(z*hh + gi)*ww + gj];
        s_rg[lrr*36 + lcx] = v;
    }
    // stage ad: g_adT[z][pos][ic] -> s_a[li][lj][ic]  (16B chunks)
    for (int t = tid; t < 10*34*4; t += 256) {
        int chunk = t & 3; int lj = (t >> 2) % 34; int li = t / 136;
        int gi = i0 - 1 + li, gj = j0 - 1 + lj;
        uint4 v = make_uint4(0,0,0,0);
        if (gi >= 0 && gi < hh && gj >= 0 && gj < ww)
            v = *reinterpret_cast<const uint4*>(
                &g_adT[(z*19200 + gi*160 + gj)*32 + chunk*8]);
        *reinterpret_cast<uint4*>(&s_a[(li*34 + lj)*40 + chunk*8]) = v;
    }
    __syncthreads();

    uint32_t sab = (uint32_t)__cvta_generic_to_shared(s_a);
    uint32_t swb = (uint32_t)__cvta_generic_to_shared(s_w2);
    int r = wid;
    int m = lane & 15;
    int koff = (lane >> 4) * 8;
    uint32_t baseA0 = sab + (uint32_t)((((r+1)*34 + (m + 1))*40 + koff) * 2);
    int nrow2 = lane & 7;
    int kboff2 = ((lane >> 3) & 1) ? 8 : 0;

    float acc[2][4];
    #pragma unroll
    for (int s = 0; s < 2; s++)
        #pragma unroll
        for (int q = 0; q < 4; q++) acc[s][q] = 0.f;

    #pragma unroll
    for (int tap = 0; tap < 9; tap++) {
        int dy = tap/3 - 1, dx = tap%3 - 1;
        int offA = (dy*34 + dx)*40*2;
        #pragma unroll
        for (int kc = 0; kc < 2; kc++) {
            uint32_t a0[4], a1[4];
            uint32_t aad = baseA0 + offA + kc*32;
            LDSM_X4(a0[0],a0[1],a0[2],a0[3], aad);
            LDSM_X4(a1[0],a1[1],a1[2],a1[3], aad + 16*40*2);
            uint32_t bad = swb + (uint32_t)(((tap*8 + nrow2)*32 + kc*16 + kboff2) * 2);
            uint32_t b0,b1;
            LDSM_X2(b0,b1, bad);
            MMA_BF16(acc[0], a0[0],a0[1],a0[2],a0[3], b0,b1);
            MMA_BF16(acc[1], a1[0],a1[1],a1[2],a1[3], b0,b1);
        }
    }

    // loss epilogue
    float num = 0.f, den = 0.f;
    int ocl = 2*(lane & 3);
    if (ocl < 4) {
        #pragma unroll
        for (int s = 0; s < 2; s++) {
            #pragma unroll
            for (int q = 0; q < 4; q++) {
                int oc = ocl + (q & 1);
                int m2 = (lane >> 2) + ((q >> 1) * 8);
                int c = s*16 + m2;
                float ds = acc[s][q] + bp[oc];
                int ox = (oc >= 1) ? 1 : 0;
                int oy = (oc < 2) ? 1 : ((oc == 2) ? 0 : -1);
                float cen = s_rg[(r+1)*36 + (c+1)];
                float nbv = s_rg[(r+1+ox)*36 + (c+1+oy)];
                float grad = __logf(cen + 1e-6f) - __logf(nbv + 1e-6f);
                float a = fabsf(ds - grad);
                float sl1 = (a < 0.01f) ? (0.5f*a*a/0.01f) : (a - 0.005f);
                if (cen > 0.1f && nbv > 0.1f) { num += sl1; den += 1.f; }
            }
        }
    }
    #pragma unroll
    for (int o = 16; o > 0; o >>= 1) {
        num += __shfl_down_sync(0xffffffffu, num, o);
        den += __shfl_down_sync(0xffffffffu, den, o);
    }
    if (lane == 0) { s_red[wid] = num; s_red[8 + wid] = den; }
    __syncthreads();
    if (tid == 0) {
        float sn = 0.f, sd = 0.f;
        #pragma unroll
        for (int w = 0; w < 8; w++) { sn += s_red[w]; sd += s_red[8+w]; }
        atomicAdd(&g_num[rr], sn);
        atomicAdd(&g_den[rr], sd);
    }
}

__global__ void k_final(float* out) {
    if (threadIdx.x == 0) {
        float tot = 0.f;
        for (int r = 0; r < RR; r++) tot += g_num[r] / g_den[r];
        out[0] = tot / 20.0f;
    }
}

extern "C" void kernel_launch(void* const* d_in, const int* in_sizes, int n_in,
                              void* d_out, int out_size) {
    const float* x    = (const float*)d_in[0];
    const float* d    = (const float*)d_in[1];
    const float* gts  = (const float*)d_in[2];
    const float* rnd  = (const float*)d_in[3];
    const float* Wa   = (const float*)d_in[4];
    const float* ba   = (const float*)d_in[5];
    const float* Wp   = (const float*)d_in[6];
    const float* bp   = (const float*)d_in[7];
    float* out = (float*)d_out;

    k_zero<<<1, 32>>>();
    k_wcvt<<<36, 256>>>(Wa, Wp);
    k_pool<<<(RR*NB*hh*ww + 255)/256, 256>>>(gts, rnd);

    dim3 bs2(32, 4), gs2(ww/32, hh/4, NB*4);
    k_sample<<<gs2, bs2>>>(x);

    dim3 bs3(256), gs3(ww/32, hh/8, RR*NB);
    k_conv1<<<gs3, bs3>>>(ba, d);

    dim3 bs4(256), gs4(ww/32, hh/8, RR*NB);
    k_conv2<<<gs4, bs4>>>(bp);

    k_final<<<1, 32>>>(out);
}